// round 17
// baseline (speedup 1.0000x reference)
#include <cuda_runtime.h>
#include <cuda_fp16.h>
#include <cstdint>

typedef unsigned int u32;
typedef unsigned long long u64;

#define H 200
#define W 704
#define HW_TOT (H*W)            // 140800
#define IHP 202
#define IWP 712
#define NPX ((size_t)IHP*IWP)   // padded pixels per plane
#define NCH 256
#define NBOX 128
#define NLAY 6

// ======================= persistent device scratch (zero-init at load) ==============
__device__ __align__(16) __half g_p0[NPX*NCH];
__device__ __align__(16) __half g_p1[NPX*NCH];
__device__ __align__(16) __half g_y [NPX*NCH];
__device__ __align__(16) __half g_wh[(size_t)NLAY*9*65536];
__device__ float g_obj[NBOX*NCH];
__device__ float g_edge[NBOX*16];
__device__ int   g_nact;
__device__ int   g_pix[HW_TOT];
__device__ uint4 g_mask[HW_TOT];

// ======================= PTX helpers (plain sm_80-class PTX) =======================
__device__ __forceinline__ u32 smem_to_u32(const void* p) {
    u32 a;
    asm("{ .reg .u64 t; cvta.to.shared.u64 t, %1; cvt.u32.u64 %0, t; }" : "=r"(a) : "l"(p));
    return a;
}
#define SWZ(o) ((o) ^ (((o) >> 3) & 0x70))

#define CP_ASYNC16(dst, src) \
    asm volatile("cp.async.cg.shared.global [%0], [%1], 16;" :: "r"(dst), "l"(src))
#define CP_COMMIT() asm volatile("cp.async.commit_group;" ::: "memory")
#define CP_WAIT1()  asm volatile("cp.async.wait_group 1;" ::: "memory")
#define CP_WAIT0()  asm volatile("cp.async.wait_group 0;" ::: "memory")

#define LDSM4(r, addr) \
    asm volatile("ldmatrix.sync.aligned.m8n8.x4.shared.b16 {%0,%1,%2,%3}, [%4];" \
        : "=r"((r)[0]), "=r"((r)[1]), "=r"((r)[2]), "=r"((r)[3]) : "r"(addr))

#define MMAH(c, a, b0_, b1_) \
    asm volatile("mma.sync.aligned.m16n8k16.row.col.f32.f16.f16.f32 " \
        "{%0,%1,%2,%3},{%4,%5,%6,%7},{%8,%9},{%0,%1,%2,%3};" \
        : "+f"((c)[0]), "+f"((c)[1]), "+f"((c)[2]), "+f"((c)[3]) \
        : "r"((a)[0]), "r"((a)[1]), "r"((a)[2]), "r"((a)[3]), "r"(b0_), "r"(b1_))

__device__ __forceinline__ float hfu(u32 bits16) {
    return __half2float(__ushort_as_half((unsigned short)bits16));
}

// ======================= MLP =======================
__global__ void mlp_kernel(const float* __restrict__ box, const float* __restrict__ score,
                           const float* __restrict__ w1, const float* __restrict__ b1,
                           const float* __restrict__ w2, const float* __restrict__ b2,
                           const float* __restrict__ w3, const float* __restrict__ b3)
{
    __shared__ float f[25];
    __shared__ float h1[256];
    __shared__ float h2[256];
    int n = blockIdx.x, c = threadIdx.x;
    if (c < 25) f[c] = (c < 24) ? box[n * 24 + c] : score[n];
    __syncthreads();
    float a = b1[c];
#pragma unroll
    for (int k = 0; k < 25; ++k) a = fmaf(f[k], w1[k * 256 + c], a);
    h1[c] = fmaxf(a, 0.0f);
    __syncthreads();
    a = b2[c];
    for (int k = 0; k < 256; ++k) a = fmaf(h1[k], w2[k * 256 + c], a);
    h2[c] = fmaxf(a, 0.0f);
    __syncthreads();
    a = b3[c];
    for (int k = 0; k < 256; ++k) a = fmaf(h2[k], w3[k * 256 + c], a);
    g_obj[n * 256 + c] = a * score[n];
}

// ======================= box edges =======================
__global__ void edge_kernel(const float* __restrict__ box)
{
    int n = threadIdx.x;
    if (n == 0) g_nact = 0;
    if (n < NBOX) {
        float gx[4], gy[4];
#pragma unroll
        for (int e = 0; e < 4; ++e) {
            gx[e] = __fdiv_rn(__fsub_rn(box[n * 24 + e * 3 + 0], -140.8f), 0.4f);
            gy[e] = __fdiv_rn(__fsub_rn(box[n * 24 + e * 3 + 1], -40.0f), 0.4f);
        }
#pragma unroll
        for (int e = 0; e < 4; ++e) {
            int e1 = (e + 1) & 3;
            g_edge[n * 16 + e * 4 + 0] = gx[e];
            g_edge[n * 16 + e * 4 + 1] = gy[e];
            g_edge[n * 16 + e * 4 + 2] = __fsub_rn(gx[e1], gx[e]);
            g_edge[n * 16 + e * 4 + 3] = __fsub_rn(gy[e1], gy[e]);
        }
    }
}

// ======================= zero p0 plane =======================
__global__ void zero_kernel(uint4* a, size_t n4)
{
    size_t i = (size_t)blockIdx.x * blockDim.x + threadIdx.x;
    size_t st = (size_t)gridDim.x * blockDim.x;
    uint4 z = make_uint4(0, 0, 0, 0);
    for (; i < n4; i += st) a[i] = z;
}

// ======================= raster mask + compaction =======================
__global__ void mask_kernel()
{
    __shared__ float se[NBOX * 16];
    int tid = threadIdx.x;
    for (int i = tid; i < NBOX * 16; i += blockDim.x) se[i] = g_edge[i];
    __syncthreads();

    int p = blockIdx.x * 256 + tid;
    if (p >= HW_TOT) return;
    int h = p / W;
    int w = p - h * W;
    float cy = (float)h + 0.5f;
    float cx = (float)w + 0.5f;

    unsigned mw[4];
    int cnt = 0;
#pragma unroll
    for (int wi = 0; wi < 4; ++wi) {
        unsigned m = 0;
        for (int b = 0; b < 32; ++b) {
            int n = wi * 32 + b;
            const float* e = &se[n * 16];
            bool ins = true;
#pragma unroll
            for (int k = 0; k < 4; ++k) {
                float ax = e[k * 4 + 0], ay = e[k * 4 + 1];
                float vx = e[k * 4 + 2], vy = e[k * 4 + 3];
                float c = __fsub_rn(__fmul_rn(vx, __fsub_rn(cy, ay)),
                                    __fmul_rn(vy, __fsub_rn(cx, ax)));
                ins = ins && (c >= 0.0f);
            }
            if (ins) m |= (1u << b);
        }
        mw[wi] = m;
        cnt += __popc(m);
    }
    if (cnt) {
        int pos = atomicAdd(&g_nact, 1);
        g_pix[pos] = p;
        g_mask[pos] = make_uint4(mw[0], mw[1], mw[2], mw[3]);
    }
}

// ======================= scatter into p0 (fp16 NHWC) =======================
__global__ void fill_kernel()
{
    int c = threadIdx.x;
    int nact = g_nact;
    for (int i = blockIdx.x; i < nact; i += gridDim.x) {
        int p = g_pix[i];
        uint4 mm = g_mask[i];
        int cnt = __popc(mm.x) + __popc(mm.y) + __popc(mm.z) + __popc(mm.w);
        float acc = 0.0f;
        unsigned m;
        m = mm.x; while (m) { int b = __ffs(m) - 1; m &= m - 1; acc += g_obj[(b)      * NCH + c]; }
        m = mm.y; while (m) { int b = __ffs(m) - 1; m &= m - 1; acc += g_obj[(b + 32) * NCH + c]; }
        m = mm.z; while (m) { int b = __ffs(m) - 1; m &= m - 1; acc += g_obj[(b + 64) * NCH + c]; }
        m = mm.w; while (m) { int b = __ffs(m) - 1; m &= m - 1; acc += g_obj[(b + 96) * NCH + c]; }
        float v = acc / (float)cnt;
        int h = p / W;
        int w = p - h * W;
        g_p0[((size_t)(h + 1) * IWP + (w + 4)) * NCH + c] = __float2half_rn(v);
    }
}

// ======================= weight convert fp32 -> fp16, [l][tap][co][ci] ==============
__global__ void wsplit_kernel(const float* __restrict__ cw)
{
    int idx = blockIdx.x * 256 + threadIdx.x;
    if (idx >= NLAY * 65536) return;
    int l = idx >> 16;
    int r = idx & 65535;           // co*256 + ci
    int co = r >> 8, ci = r & 255;
    const float* src = cw + (((size_t)l * 256 + co) * 256 + ci) * 9;
#pragma unroll
    for (int t = 0; t < 9; ++t) {
        g_wh[(size_t)(l * 9 + t) * 65536 + r] = __float2half_rn(src[t]);
    }
}

// ======================= fp16 mma conv3x3 + BN (+res) + ReLU =======================
// CTA: 512 thr (16 warps, 4 wm x 4 wn; warp tile m=32 x n=64).
// Tile: M=128 px x N=256 co (halves B traffic vs M=64). 36 stages = 9 taps x 4 ci64.
// Stage: A 16K | B 32K = 48KB, double buffered (96KB/CTA).
#define STG 49152
#define SMEM_CONV (2*STG + 2048 + 128)

__device__ __forceinline__ void issue_stage(
    u32 db, int buf, int it, int h0, int w0, int tid,
    const __half* __restrict__ inP, const __half* __restrict__ wH)
{
    int tap = it >> 2, q = it & 3;
    int kh = tap / 3, kw = tap - kh * 3;
    int ci0 = q * 64;
    u32 Ab = db + buf * STG;
    // A: 128 px rows x 128B; 1024 chunks, 2/thread
    size_t abase = ((size_t)(h0 + kh) * IWP + (size_t)(w0 + 3 + kw)) * NCH + ci0;
#pragma unroll
    for (int k = 0; k < 2; ++k) {
        int idx = tid + k * 512;           // 0..1023
        int m = idx >> 3, j = idx & 7;
        CP_ASYNC16(Ab + SWZ((u32)(m * 128 + j * 16)), inP + abase + (size_t)m * NCH + j * 8);
    }
    // B: 256 co rows x 128B; 2048 chunks, 4/thread
    size_t wbase = (size_t)tap * 65536 + ci0;
    u32 Bb = Ab + 16384;
#pragma unroll
    for (int k = 0; k < 4; ++k) {
        int idx = tid + k * 512;           // 0..2047
        int co = idx >> 3, j = idx & 7;
        CP_ASYNC16(Bb + SWZ((u32)(co * 128 + j * 16)), wH + wbase + (size_t)co * NCH + j * 8);
    }
}

__global__ __launch_bounds__(512, 1)
void conv_mma(const __half* __restrict__ inP, const __half* __restrict__ wH,
              const float* __restrict__ bng, const float* __restrict__ bnb,
              const float* __restrict__ bnm, const float* __restrict__ bnv,
              const __half* resP, __half* outP, float* outF)
{
    extern __shared__ char smem_raw[];
    u32 sb = smem_to_u32(smem_raw);
    u32 pd = (128u - (sb & 127u)) & 127u;
    char* dyn = smem_raw + pd;
    u32 db = sb + pd;
    float* ssc = (float*)(dyn + 2 * STG);
    float* ssh = ssc + 256;

    int tid  = threadIdx.x;
    int lane = tid & 31, warp = tid >> 5;
    int wm = warp & 3, wn = warp >> 2;          // 4 x 4 warp grid
    int h0 = blockIdx.y;
    int wt = blockIdx.x;
    int w0 = (wt == 5) ? 576 : wt * 128;        // overlap tile 5 (deterministic dup)

    if (tid < 256) {   // BN affine per channel
        float sc = bng[tid] * rsqrtf(bnv[tid] + 1e-5f);
        ssc[tid] = sc;
        ssh[tid] = bnb[tid] - bnm[tid] * sc;
    }

    float acc[2][8][4];
#pragma unroll
    for (int a = 0; a < 2; ++a)
#pragma unroll
        for (int b = 0; b < 8; ++b)
#pragma unroll
            for (int c = 0; c < 4; ++c) acc[a][b][c] = 0.0f;

    issue_stage(db, 0, 0, h0, w0, tid, inP, wH);
    CP_COMMIT();

    int lrow = lane & 15;
    int lkb  = (lane >> 4) << 4;       // 0 or 16 bytes (k0/k8)

    for (int it = 0; it < 36; ++it) {
        if (it + 1 < 36) {
            issue_stage(db, (it + 1) & 1, it + 1, h0, w0, tid, inP, wH);
            CP_COMMIT();
            CP_WAIT1();
        } else {
            CP_WAIT0();
        }
        __syncthreads();

        u32 Ab = db + (it & 1) * STG;
        u32 Bb = Ab + 16384;

#pragma unroll
        for (int st = 0; st < 4; ++st) {
            int kb = st * 32 + lkb;
            u32 af[2][4];
#pragma unroll
            for (int mf = 0; mf < 2; ++mf) {
                LDSM4(af[mf], Ab + SWZ((u32)((wm * 32 + mf * 16 + lrow) * 128 + kb)));
            }
#pragma unroll
            for (int bp = 0; bp < 4; ++bp) {
                u32 bf[4];
                LDSM4(bf, Bb + SWZ((u32)((wn * 64 + bp * 16 + lrow) * 128 + kb)));
#pragma unroll
                for (int mf = 0; mf < 2; ++mf) {
                    MMAH(acc[mf][2 * bp],     af[mf], bf[0], bf[2]);
                    MMAH(acc[mf][2 * bp + 1], af[mf], bf[1], bf[3]);
                }
            }
        }
        __syncthreads();
    }

    // ---- epilogue: BN, residual, ReLU, store ----
#pragma unroll
    for (int mf = 0; mf < 2; ++mf) {
#pragma unroll
        for (int r2 = 0; r2 < 2; ++r2) {
            int m = wm * 32 + mf * 16 + (lane >> 2) + r2 * 8;   // 0..127
            int wpix = w0 + m;
            size_t pb = ((size_t)(h0 + 1) * IWP + (size_t)(wpix + 4)) * NCH;
#pragma unroll
            for (int a = 0; a < 8; ++a) {
                int n = wn * 64 + a * 8 + (lane & 3) * 2;
                float v0 = fmaf(acc[mf][a][r2 * 2 + 0], ssc[n],     ssh[n]);
                float v1 = fmaf(acc[mf][a][r2 * 2 + 1], ssc[n + 1], ssh[n + 1]);
                if (resP) {
                    u32 rh = *(const u32*)((const char*)resP + (pb + n) * 2);
                    v0 += hfu(rh & 0xffffu);
                    v1 += hfu(rh >> 16);
                }
                v0 = fmaxf(v0, 0.0f);
                v1 = fmaxf(v1, 0.0f);
                if (outP) {
                    u32 hp = (u32)__half_as_ushort(__float2half_rn(v0))
                           | ((u32)__half_as_ushort(__float2half_rn(v1)) << 16);
                    *(u32*)((char*)outP + (pb + n) * 2) = hp;
                } else {
                    outF[(size_t)n * HW_TOT       + (size_t)h0 * W + wpix] = v0;
                    outF[(size_t)(n + 1) * HW_TOT + (size_t)h0 * W + wpix] = v1;
                }
            }
        }
    }
}

// ======================= host launcher =======================
extern "C" void kernel_launch(void* const* d_in, const int* in_sizes, int n_in,
                              void* d_out, int out_size)
{
    const float* box   = (const float*)d_in[0];
    const float* score = (const float*)d_in[1];
    const float* w1 = (const float*)d_in[2];
    const float* b1 = (const float*)d_in[3];
    const float* w2 = (const float*)d_in[4];
    const float* b2 = (const float*)d_in[5];
    const float* w3 = (const float*)d_in[6];
    const float* b3 = (const float*)d_in[7];
    const float* cw = (const float*)d_in[8];
    const float* bg = (const float*)d_in[9];
    const float* bb = (const float*)d_in[10];
    const float* bm = (const float*)d_in[11];
    const float* bv = (const float*)d_in[12];

    cudaFuncSetAttribute(conv_mma, cudaFuncAttributeMaxDynamicSharedMemorySize, SMEM_CONV);

    __half *p0, *p1, *yP, *wh;
    cudaGetSymbolAddress((void**)&p0, g_p0);
    cudaGetSymbolAddress((void**)&p1, g_p1);
    cudaGetSymbolAddress((void**)&yP, g_y);
    cudaGetSymbolAddress((void**)&wh, g_wh);

    mlp_kernel<<<128, 256>>>(box, score, w1, b1, w2, b2, w3, b3);
    edge_kernel<<<1, 128>>>(box);
    wsplit_kernel<<<(NLAY * 65536 + 255) / 256, 256>>>(cw);
    zero_kernel<<<2048, 256>>>((uint4*)p0, NPX * NCH / 8);
    mask_kernel<<<HW_TOT / 256, 256>>>();
    fill_kernel<<<1024, 256>>>();

    dim3 grid(6, 200);       // 6 w-tiles(128, last overlapping) x 200 rows
    const size_t WSTRIDE = (size_t)9 * 65536;
    // blk0: p0 -> y ; (y, res p0) -> p1
    conv_mma<<<grid, 512, SMEM_CONV>>>(p0, wh + 0 * WSTRIDE,
        bg + 0, bb + 0, bm + 0, bv + 0, nullptr, yP, nullptr);
    conv_mma<<<grid, 512, SMEM_CONV>>>(yP, wh + 1 * WSTRIDE,
        bg + 256, bb + 256, bm + 256, bv + 256, p0, p1, nullptr);
    // blk1: p1 -> y ; (y, res p1) -> p0
    conv_mma<<<grid, 512, SMEM_CONV>>>(p1, wh + 2 * WSTRIDE,
        bg + 512, bb + 512, bm + 512, bv + 512, nullptr, yP, nullptr);
    conv_mma<<<grid, 512, SMEM_CONV>>>(yP, wh + 3 * WSTRIDE,
        bg + 768, bb + 768, bm + 768, bv + 768, p1, p0, nullptr);
    // blk2: p0 -> y ; (y, res p0) -> d_out (fp32 NCHW)
    conv_mma<<<grid, 512, SMEM_CONV>>>(p0, wh + 4 * WSTRIDE,
        bg + 1024, bb + 1024, bm + 1024, bv + 1024, nullptr, yP, nullptr);
    conv_mma<<<grid, 512, SMEM_CONV>>>(yP, wh + 5 * WSTRIDE,
        bg + 1280, bb + 1280, bm + 1280, bv + 1280, p0, nullptr, (float*)d_out);
}